// round 7
// baseline (speedup 1.0000x reference)
#include <cuda_runtime.h>
#include <cuda_fp16.h>
#include <cstdint>
#include <math.h>

#define NTOK  4096
#define HDIM  1024
#define IDIM  1024
#define NEXP  8
#define TOPK  4
#define GUDIM 2048

#define MT 256
#define NT 128
#define KT 64
#define NCHUNK 16

// smem: [0,1024) row ints, then 2 stages of (A 256x72 + B 128x72) halves
#define TILE_A  (256 * 72 * 2)           // 36864 B
#define TILE_B  (128 * 72 * 2)           // 18432 B
#define STAGE   (TILE_A + TILE_B)        // 55296 B
#define SMEM_TOTAL (1024 + 2 * STAGE)    // 111616 B -> 1 CTA/SM

// ---------------- device scratch ----------------------------------------------------
__device__ __align__(16) __half g_xh [(size_t)NTOK * HDIM];
__device__ __align__(16) __half g_w1h[(size_t)NEXP * GUDIM * HDIM];   // [e][n][k]
__device__ __align__(16) __half g_w2h[(size_t)NEXP * HDIM * IDIM];    // [e][n][k]
__device__ __align__(16) __half g_act[(size_t)NEXP * NTOK * IDIM];
__device__ __align__(16) float  g_ebuf[(size_t)NTOK * TOPK * HDIM];
__device__ int g_count[NEXP];
__device__ int g_assign[NEXP * NTOK];

// ---------------- helpers -----------------------------------------------------------
__device__ __forceinline__ uint32_t smem_u32(const void* p) {
    uint32_t a;
    asm("{ .reg .u64 t; cvta.to.shared.u64 t, %1; cvt.u32.u64 %0, t; }" : "=r"(a) : "l"(p));
    return a;
}

#define CPA16(dst, src)       asm volatile("cp.async.cg.shared.global [%0], [%1], 16;"     :: "r"(dst), "l"(src))
#define CPA16P(dst, src, sz)  asm volatile("cp.async.cg.shared.global [%0], [%1], 16, %2;" :: "r"(dst), "l"(src), "r"(sz))
#define CPA_COMMIT()          asm volatile("cp.async.commit_group;" ::: "memory")
#define CPA_WAIT(n)           asm volatile("cp.async.wait_group %0;" :: "n"(n) : "memory")

__device__ __forceinline__ void ldsm4(uint32_t& r0, uint32_t& r1, uint32_t& r2, uint32_t& r3,
                                      uint32_t addr) {
    asm volatile("ldmatrix.sync.aligned.m8n8.x4.shared.b16 {%0,%1,%2,%3}, [%4];"
                 : "=r"(r0), "=r"(r1), "=r"(r2), "=r"(r3) : "r"(addr));
}
__device__ __forceinline__ void mma16816(float* d, const uint32_t* a, uint32_t b0, uint32_t b1) {
    asm volatile("mma.sync.aligned.m16n8k16.row.col.f32.f16.f16.f32 "
                 "{%0,%1,%2,%3},{%4,%5,%6,%7},{%8,%9},{%0,%1,%2,%3};"
                 : "+f"(d[0]), "+f"(d[1]), "+f"(d[2]), "+f"(d[3])
                 : "r"(a[0]), "r"(a[1]), "r"(a[2]), "r"(a[3]), "r"(b0), "r"(b1));
}

// ---------------- tiny utility kernels ----------------------------------------------
__global__ void zero_counts_kernel() {
    if (threadIdx.x < NEXP) g_count[threadIdx.x] = 0;
}

__global__ void cvt_x_kernel(const float* __restrict__ s) {
    int stride = gridDim.x * blockDim.x;
    int n4 = NTOK * HDIM / 4;
    for (int i = blockIdx.x * blockDim.x + threadIdx.x; i < n4; i += stride) {
        float4 v = ((const float4*)s)[i];
        __half2* d = (__half2*)(g_xh + (size_t)i * 4);
        d[0] = __floats2half2_rn(v.x, v.y);
        d[1] = __floats2half2_rn(v.z, v.w);
    }
}

// transpose-convert: s [z][K][N] fp32 -> d [z][N][K] fp16 (half2 coalesced writes)
__global__ void cvt_t_kernel(const float* __restrict__ s, __half* __restrict__ d,
                             int K, int N) {
    __shared__ float t[32][33];
    int n0 = blockIdx.x * 32, k0 = blockIdx.y * 32, z = blockIdx.z;
    const float* sp = s + (size_t)z * K * N;
    __half* dp = d + (size_t)z * K * N;
    int tx = threadIdx.x, ty = threadIdx.y;
#pragma unroll
    for (int i = 0; i < 32; i += 8)
        t[ty + i][tx] = sp[(size_t)(k0 + ty + i) * N + n0 + tx];
    __syncthreads();
    int id = ty * 32 + tx;
#pragma unroll
    for (int j = 0; j < 2; j++) {
        int v = id + j * 256;
        int r = v >> 4;
        int c = v & 15;
        __half2 h = __floats2half2_rn(t[c * 2][r], t[c * 2 + 1][r]);
        *(__half2*)(dp + (size_t)(n0 + r) * K + k0 + c * 2) = h;
    }
}

// ---------------- router ------------------------------------------------------------
__global__ void router_kernel(const float* __restrict__ x,
                              const float* __restrict__ rw,
                              const float* __restrict__ rb,
                              float* __restrict__ ew_out) {
    int warp = (blockIdx.x * blockDim.x + threadIdx.x) >> 5;
    int lane = threadIdx.x & 31;
    if (warp >= NTOK) return;
    const float* xr = x + (size_t)warp * HDIM;

    float acc[NEXP];
#pragma unroll
    for (int e = 0; e < NEXP; e++) acc[e] = 0.f;
    for (int h = lane; h < HDIM; h += 32) {
        float xv = xr[h];
#pragma unroll
        for (int e = 0; e < NEXP; e++) acc[e] += xv * rw[e * HDIM + h];
    }
#pragma unroll
    for (int e = 0; e < NEXP; e++) {
#pragma unroll
        for (int off = 16; off; off >>= 1)
            acc[e] += __shfl_xor_sync(0xffffffffu, acc[e], off);
    }
    if (lane == 0) {
        float lg[NEXP];
#pragma unroll
        for (int e = 0; e < NEXP; e++) lg[e] = acc[e] + rb[e];
        int idx[TOPK]; float val[TOPK]; bool used[NEXP];
#pragma unroll
        for (int e = 0; e < NEXP; e++) used[e] = false;
        for (int k = 0; k < TOPK; k++) {
            float best = -INFINITY; int bi = 0;
            for (int e = 0; e < NEXP; e++)
                if (!used[e] && lg[e] > best) { best = lg[e]; bi = e; }
            used[bi] = true; idx[k] = bi; val[k] = best;
        }
        float m = val[0], s = 0.f, w[TOPK];
        for (int k = 0; k < TOPK; k++) { w[k] = expf(val[k] - m); s += w[k]; }
        float inv = 1.f / s;
        for (int k = 0; k < TOPK; k++) {
            w[k] *= inv;
            ew_out[warp * TOPK + k] = w[k];
            int p = atomicAdd(&g_count[idx[k]], 1);
            g_assign[idx[k] * NTOK + p] = warp * 4 + k;
        }
    }
}

// ====================================================================================
// GEMM1: act = SwiGLU(gather(x) @ w1^T + b1)  (256 thr, 8 warps 4x2, warp tile 64x64)
// ====================================================================================
__global__ __launch_bounds__(256, 1)
void gemm1_kernel(const float* __restrict__ b1) {
    extern __shared__ char smem[];
    const int e    = blockIdx.z;
    const int cnt  = g_count[e];
    const int row0 = blockIdx.y * MT;
    if (row0 >= cnt) return;
    const int col0 = blockIdx.x * NT;
    const int tid = threadIdx.x, lane = tid & 31, wid = tid >> 5;
    const int wm = wid >> 1, wn = wid & 1;   // 4 x 2
    uint32_t sb = smem_u32(smem);
    int* s_tok = (int*)smem;

    {
        int r = row0 + tid;
        s_tok[tid] = (r < cnt) ? (g_assign[e * NTOK + r] >> 2) : -1;
    }
    __syncthreads();

    float d[4][8][4];
#pragma unroll
    for (int mi = 0; mi < 4; mi++)
#pragma unroll
        for (int nt = 0; nt < 8; nt++)
#pragma unroll
            for (int r = 0; r < 4; r++) d[mi][nt][r] = 0.f;

    const __half* Bb = g_w1h + ((size_t)e * GUDIM + col0) * HDIM;
    const int lr = tid >> 3, lc = tid & 7;   // 32 rows-per-pass x 8 col-slots

    auto issue = [&](int cidx) {
        int p = cidx & 1, kt = cidx * KT;
        uint32_t a0 = sb + 1024 + p * STAGE;
        uint32_t b0 = a0 + TILE_A;
#pragma unroll
        for (int i = 0; i < 8; i++) {       // A: 256 rows
            int r = lr + i * 32;
            int tok = s_tok[r];
            CPA16P(a0 + (r * 72 + lc * 8) * 2,
                   g_xh + (size_t)(tok < 0 ? 0 : tok) * HDIM + kt + lc * 8,
                   (tok >= 0) ? 16 : 0);
        }
#pragma unroll
        for (int i = 0; i < 4; i++) {       // B: 128 rows
            int r = lr + i * 32;
            CPA16(b0 + (r * 72 + lc * 8) * 2, Bb + (size_t)r * HDIM + kt + lc * 8);
        }
        CPA_COMMIT();
    };

    issue(0);
    for (int cc = 0; cc < NCHUNK; cc++) {
        int p = cc & 1;
        if (cc + 1 < NCHUNK) { issue(cc + 1); CPA_WAIT(1); }
        else                 { CPA_WAIT(0); }
        __syncthreads();
        uint32_t sA = sb + 1024 + p * STAGE;
        uint32_t sB = sA + TILE_A;
        uint32_t aBase = sA + ((wm * 64 + (lane & 15)) * 72 + (lane >> 4) * 8) * 2;
        uint32_t bBase = sB + ((wn * 64 + (lane & 7) + (lane >> 4) * 8) * 72 +
                               ((lane >> 3) & 1) * 8) * 2;
#pragma unroll
        for (int kk = 0; kk < KT; kk += 16) {
            uint32_t a[4][4], b[4][4];
#pragma unroll
            for (int mi = 0; mi < 4; mi++)
                ldsm4(a[mi][0], a[mi][1], a[mi][2], a[mi][3],
                      aBase + (mi * 16 * 72 + kk) * 2);
#pragma unroll
            for (int g = 0; g < 4; g++)
                ldsm4(b[g][0], b[g][1], b[g][2], b[g][3],
                      bBase + (g * 16 * 72 + kk) * 2);
#pragma unroll
            for (int mi = 0; mi < 4; mi++)
#pragma unroll
                for (int g = 0; g < 4; g++) {
                    mma16816(d[mi][2 * g],     a[mi], b[g][0], b[g][1]);
                    mma16816(d[mi][2 * g + 1], a[mi], b[g][2], b[g][3]);
                }
        }
        __syncthreads();
    }

    // epilogue: SwiGLU straight from register pairs (d0,d1)=(gate,up) row q; (d2,d3) row q+8
    // stage act halves: [256 rows][64 act cols]
    __half* st_h = (__half*)(smem + 1024);
    const float* bb = b1 + e * GUDIM + col0;
#pragma unroll
    for (int mi = 0; mi < 4; mi++) {
        int rbase = wm * 64 + mi * 16 + (lane >> 2);
#pragma unroll
        for (int nt = 0; nt < 8; nt++) {
            int gcl = wn * 64 + nt * 8 + (lane & 3) * 2;   // local gate col (even)
            float bg = bb[gcl], bu = bb[gcl + 1];
            int acl = (gcl >> 1);                          // local act col 0..63
#pragma unroll
            for (int h = 0; h < 2; h++) {
                float g = d[mi][nt][2 * h]     + bg;
                float u = d[mi][nt][2 * h + 1] + bu;
                g = fminf(g, 7.0f);
                u = fminf(fmaxf(u, -7.0f), 7.0f);
                float glu = g / (1.0f + expf(-1.702f * g));
                st_h[(rbase + 8 * h) * 64 + acl] = __float2half((u + 1.0f) * glu);
            }
        }
    }
    __syncthreads();
    {
        int rg = row0 + tid;
        if (rg < cnt) {
            __half* dst = g_act + ((size_t)e * NTOK + rg) * IDIM + (col0 >> 1);
            const int4* src = (const int4*)(st_h + tid * 64);
            *(int4*)(dst)     = src[0];
            *(int4*)(dst + 8) = src[1];
            *(int4*)(dst + 16) = src[2];
            *(int4*)(dst + 24) = src[3];
            *(int4*)(dst + 32) = src[4];
            *(int4*)(dst + 40) = src[5];
            *(int4*)(dst + 48) = src[6];
            *(int4*)(dst + 56) = src[7];
        }
    }
}

// ====================================================================================
// GEMM2: ebuf[assign] = act @ w2^T + b2   (direct float2 stores from registers)
// ====================================================================================
__global__ __launch_bounds__(256, 1)
void gemm2_kernel(const float* __restrict__ b2) {
    extern __shared__ char smem[];
    const int e    = blockIdx.z;
    const int cnt  = g_count[e];
    const int row0 = blockIdx.y * MT;
    if (row0 >= cnt) return;
    const int col0 = blockIdx.x * NT;
    const int tid = threadIdx.x, lane = tid & 31, wid = tid >> 5;
    const int wm = wid >> 1, wn = wid & 1;
    uint32_t sb = smem_u32(smem);
    int* s_asn = (int*)smem;

    {
        int r = row0 + tid;
        s_asn[tid] = (r < cnt) ? g_assign[e * NTOK + r] : -1;
    }
    __syncthreads();

    float d[4][8][4];
#pragma unroll
    for (int mi = 0; mi < 4; mi++)
#pragma unroll
        for (int nt = 0; nt < 8; nt++)
#pragma unroll
            for (int r = 0; r < 4; r++) d[mi][nt][r] = 0.f;

    const __half* Ab = g_act + ((size_t)e * NTOK + row0) * IDIM;
    const __half* Bb = g_w2h + (size_t)e * HDIM * IDIM + (size_t)col0 * IDIM;
    const int lr = tid >> 3, lc = tid & 7;

    auto issue = [&](int cidx) {
        int p = cidx & 1, kt = cidx * KT;
        uint32_t a0 = sb + 1024 + p * STAGE;
        uint32_t b0 = a0 + TILE_A;
#pragma unroll
        for (int i = 0; i < 8; i++) {
            int r = lr + i * 32;
            int ok = (s_asn[r] >= 0) ? 16 : 0;
            CPA16P(a0 + (r * 72 + lc * 8) * 2, Ab + (size_t)r * IDIM + kt + lc * 8, ok);
        }
#pragma unroll
        for (int i = 0; i < 4; i++) {
            int r = lr + i * 32;
            CPA16(b0 + (r * 72 + lc * 8) * 2, Bb + (size_t)r * IDIM + kt + lc * 8);
        }
        CPA_COMMIT();
    };

    issue(0);
    for (int cc = 0; cc < NCHUNK; cc++) {
        int p = cc & 1;
        if (cc + 1 < NCHUNK) { issue(cc + 1); CPA_WAIT(1); }
        else                 { CPA_WAIT(0); }
        __syncthreads();
        uint32_t sA = sb + 1024 + p * STAGE;
        uint32_t sB = sA + TILE_A;
        uint32_t aBase = sA + ((wm * 64 + (lane & 15)) * 72 + (lane >> 4) * 8) * 2;
        uint32_t bBase = sB + ((wn * 64 + (lane & 7) + (lane >> 4) * 8) * 72 +
                               ((lane >> 3) & 1) * 8) * 2;
#pragma unroll
        for (int kk = 0; kk < KT; kk += 16) {
            uint32_t a[4][4], b[4][4];
#pragma unroll
            for (int mi = 0; mi < 4; mi++)
                ldsm4(a[mi][0], a[mi][1], a[mi][2], a[mi][3],
                      aBase + (mi * 16 * 72 + kk) * 2);
#pragma unroll
            for (int g = 0; g < 4; g++)
                ldsm4(b[g][0], b[g][1], b[g][2], b[g][3],
                      bBase + (g * 16 * 72 + kk) * 2);
#pragma unroll
            for (int mi = 0; mi < 4; mi++)
#pragma unroll
                for (int g = 0; g < 4; g++) {
                    mma16816(d[mi][2 * g],     a[mi], b[g][0], b[g][1]);
                    mma16816(d[mi][2 * g + 1], a[mi], b[g][2], b[g][3]);
                }
        }
        __syncthreads();
    }

    // epilogue: bias + direct float2 scatter (coalesced per quad)
    const float* bb = b2 + e * HDIM + col0;
#pragma unroll
    for (int mi = 0; mi < 4; mi++) {
        int rbase = wm * 64 + mi * 16 + (lane >> 2);
#pragma unroll
        for (int h = 0; h < 2; h++) {
            int rl = rbase + 8 * h;
            int a = s_asn[rl];
            if (a >= 0) {
                float* dst = g_ebuf + (size_t)a * HDIM + col0;
#pragma unroll
                for (int nt = 0; nt < 8; nt++) {
                    int cl = wn * 64 + nt * 8 + (lane & 3) * 2;
                    float2 o;
                    o.x = d[mi][nt][2 * h]     + bb[cl];
                    o.y = d[mi][nt][2 * h + 1] + bb[cl + 1];
                    *(float2*)(dst + cl) = o;
                }
            }
        }
    }
}

// ---------------- combine -----------------------------------------------------------
__global__ void combine_kernel(float* __restrict__ out) {
    const float* ew = out + (size_t)NTOK * HDIM;
    int stride = gridDim.x * blockDim.x;
    int n4 = NTOK * HDIM / 4;
    for (int v = blockIdx.x * blockDim.x + threadIdx.x; v < n4; v += stride) {
        int t  = v >> 8;
        int hc = v & 255;
        float w0 = ew[t * 4 + 0], w1v = ew[t * 4 + 1];
        float w2v = ew[t * 4 + 2], w3 = ew[t * 4 + 3];
        const float4* e0 = (const float4*)(g_ebuf + (size_t)(t * 4 + 0) * HDIM);
        const float4* e1 = (const float4*)(g_ebuf + (size_t)(t * 4 + 1) * HDIM);
        const float4* e2 = (const float4*)(g_ebuf + (size_t)(t * 4 + 2) * HDIM);
        const float4* e3 = (const float4*)(g_ebuf + (size_t)(t * 4 + 3) * HDIM);
        float4 r0 = e0[hc], r1 = e1[hc], r2 = e2[hc], r3 = e3[hc];
        float4 o;
        o.x = w0 * r0.x + w1v * r1.x + w2v * r2.x + w3 * r3.x;
        o.y = w0 * r0.y + w1v * r1.y + w2v * r2.y + w3 * r3.y;
        o.z = w0 * r0.z + w1v * r1.z + w2v * r2.z + w3 * r3.z;
        o.w = w0 * r0.w + w1v * r1.w + w2v * r2.w + w3 * r3.w;
        ((float4*)out)[v] = o;
    }
}

// ---------------- launch ------------------------------------------------------------
extern "C" void kernel_launch(void* const* d_in, const int* in_sizes, int n_in,
                              void* d_out, int out_size) {
    const float* x  = (const float*)d_in[0];
    const float* rw = (const float*)d_in[1];
    const float* rb = (const float*)d_in[2];
    const float* w1 = (const float*)d_in[3];
    const float* b1 = (const float*)d_in[4];
    const float* w2 = (const float*)d_in[5];
    const float* b2 = (const float*)d_in[6];
    float* out = (float*)d_out;

    cudaFuncSetAttribute(gemm1_kernel, cudaFuncAttributeMaxDynamicSharedMemorySize, SMEM_TOTAL);
    cudaFuncSetAttribute(gemm2_kernel, cudaFuncAttributeMaxDynamicSharedMemorySize, SMEM_TOTAL);

    zero_counts_kernel<<<1, 32>>>();
    cvt_x_kernel<<<1024, 256>>>(x);

    __half* w1h; cudaGetSymbolAddress((void**)&w1h, g_w1h);
    __half* w2h; cudaGetSymbolAddress((void**)&w2h, g_w2h);
    cvt_t_kernel<<<dim3(GUDIM / 32, HDIM / 32, NEXP), dim3(32, 8)>>>(w1, w1h, HDIM, GUDIM);
    cvt_t_kernel<<<dim3(HDIM / 32, IDIM / 32, NEXP), dim3(32, 8)>>>(w2, w2h, IDIM, HDIM);

    router_kernel<<<NTOK / 8, 256>>>(x, rw, rb, out + (size_t)NTOK * HDIM);

    gemm1_kernel<<<dim3(GUDIM / NT, NTOK / MT, NEXP), 256, SMEM_TOTAL>>>(b1);
    gemm2_kernel<<<dim3(HDIM  / NT, NTOK / MT, NEXP), 256, SMEM_TOTAL>>>(b2);

    combine_kernel<<<2048, 256>>>(out);
}

// round 8
// speedup vs baseline: 1.2959x; 1.2959x over previous
#include <cuda_runtime.h>
#include <cuda_fp16.h>
#include <cstdint>
#include <math.h>

#define NTOK  4096
#define HDIM  1024
#define IDIM  1024
#define NEXP  8
#define TOPK  4
#define GUDIM 2048

#define MT 128
#define NT 128
#define KT 64
#define NCHUNK 16

// smem: [0,512) row ints, buffers at 1024: 2 stages of (A 128x72 + B 128x72) halves
#define FB_TILE  (128 * 72 * 2)          // 18432 B
#define FB_STAGE (2 * FB_TILE)           // 36864 B
#define SMEM_TOTAL (1024 + 2 * FB_STAGE) // 74752 B -> 2 CTAs/SM

// ---------------- device scratch ----------------------------------------------------
__device__ __align__(16) __half g_xh [(size_t)NTOK * HDIM];
__device__ __align__(16) __half g_w1h[(size_t)NEXP * GUDIM * HDIM];   // [e][n][k]
__device__ __align__(16) __half g_w2h[(size_t)NEXP * HDIM * IDIM];    // [e][n][k]
__device__ __align__(16) __half g_act[(size_t)NEXP * NTOK * IDIM];
__device__ __align__(16) float  g_ebuf[(size_t)NTOK * TOPK * HDIM];
__device__ int g_count[NEXP];
__device__ int g_assign[NEXP * NTOK];

// ---------------- helpers -----------------------------------------------------------
__device__ __forceinline__ uint32_t smem_u32(const void* p) {
    uint32_t a;
    asm("{ .reg .u64 t; cvta.to.shared.u64 t, %1; cvt.u32.u64 %0, t; }" : "=r"(a) : "l"(p));
    return a;
}

#define CPA16(dst, src)       asm volatile("cp.async.cg.shared.global [%0], [%1], 16;"     :: "r"(dst), "l"(src))
#define CPA16P(dst, src, sz)  asm volatile("cp.async.cg.shared.global [%0], [%1], 16, %2;" :: "r"(dst), "l"(src), "r"(sz))
#define CPA_COMMIT()          asm volatile("cp.async.commit_group;" ::: "memory")
#define CPA_WAIT(n)           asm volatile("cp.async.wait_group %0;" :: "n"(n) : "memory")

__device__ __forceinline__ void ldsm4(uint32_t& r0, uint32_t& r1, uint32_t& r2, uint32_t& r3,
                                      uint32_t addr) {
    asm volatile("ldmatrix.sync.aligned.m8n8.x4.shared.b16 {%0,%1,%2,%3}, [%4];"
                 : "=r"(r0), "=r"(r1), "=r"(r2), "=r"(r3) : "r"(addr));
}
__device__ __forceinline__ void mma16816(float* d, const uint32_t* a, uint32_t b0, uint32_t b1) {
    asm volatile("mma.sync.aligned.m16n8k16.row.col.f32.f16.f16.f32 "
                 "{%0,%1,%2,%3},{%4,%5,%6,%7},{%8,%9},{%0,%1,%2,%3};"
                 : "+f"(d[0]), "+f"(d[1]), "+f"(d[2]), "+f"(d[3])
                 : "r"(a[0]), "r"(a[1]), "r"(a[2]), "r"(a[3]), "r"(b0), "r"(b1));
}

// ---------------- tiny utility kernels ----------------------------------------------
__global__ void zero_counts_kernel() {
    if (threadIdx.x < NEXP) g_count[threadIdx.x] = 0;
}

__global__ void cvt_x_kernel(const float* __restrict__ s) {
    int stride = gridDim.x * blockDim.x;
    int n4 = NTOK * HDIM / 4;
    for (int i = blockIdx.x * blockDim.x + threadIdx.x; i < n4; i += stride) {
        float4 v = ((const float4*)s)[i];
        __half2* d = (__half2*)(g_xh + (size_t)i * 4);
        d[0] = __floats2half2_rn(v.x, v.y);
        d[1] = __floats2half2_rn(v.z, v.w);
    }
}

// transpose-convert: s [z][K][N] fp32 -> d [z][N][K] fp16 (half2 coalesced writes)
__global__ void cvt_t_kernel(const float* __restrict__ s, __half* __restrict__ d,
                             int K, int N) {
    __shared__ float t[32][33];
    int n0 = blockIdx.x * 32, k0 = blockIdx.y * 32, z = blockIdx.z;
    const float* sp = s + (size_t)z * K * N;
    __half* dp = d + (size_t)z * K * N;
    int tx = threadIdx.x, ty = threadIdx.y;
#pragma unroll
    for (int i = 0; i < 32; i += 8)
        t[ty + i][tx] = sp[(size_t)(k0 + ty + i) * N + n0 + tx];
    __syncthreads();
    int id = ty * 32 + tx;
#pragma unroll
    for (int j = 0; j < 2; j++) {
        int v = id + j * 256;
        int r = v >> 4;
        int c = v & 15;
        __half2 h = __floats2half2_rn(t[c * 2][r], t[c * 2 + 1][r]);
        *(__half2*)(dp + (size_t)(n0 + r) * K + k0 + c * 2) = h;
    }
}

// ---------------- router ------------------------------------------------------------
__global__ void router_kernel(const float* __restrict__ x,
                              const float* __restrict__ rw,
                              const float* __restrict__ rb,
                              float* __restrict__ ew_out) {
    int warp = (blockIdx.x * blockDim.x + threadIdx.x) >> 5;
    int lane = threadIdx.x & 31;
    if (warp >= NTOK) return;
    const float* xr = x + (size_t)warp * HDIM;

    float acc[NEXP];
#pragma unroll
    for (int e = 0; e < NEXP; e++) acc[e] = 0.f;
    for (int h = lane; h < HDIM; h += 32) {
        float xv = xr[h];
#pragma unroll
        for (int e = 0; e < NEXP; e++) acc[e] += xv * rw[e * HDIM + h];
    }
#pragma unroll
    for (int e = 0; e < NEXP; e++) {
#pragma unroll
        for (int off = 16; off; off >>= 1)
            acc[e] += __shfl_xor_sync(0xffffffffu, acc[e], off);
    }
    if (lane == 0) {
        float lg[NEXP];
#pragma unroll
        for (int e = 0; e < NEXP; e++) lg[e] = acc[e] + rb[e];
        int idx[TOPK]; float val[TOPK]; bool used[NEXP];
#pragma unroll
        for (int e = 0; e < NEXP; e++) used[e] = false;
        for (int k = 0; k < TOPK; k++) {
            float best = -INFINITY; int bi = 0;
            for (int e = 0; e < NEXP; e++)
                if (!used[e] && lg[e] > best) { best = lg[e]; bi = e; }
            used[bi] = true; idx[k] = bi; val[k] = best;
        }
        float m = val[0], s = 0.f, w[TOPK];
        for (int k = 0; k < TOPK; k++) { w[k] = expf(val[k] - m); s += w[k]; }
        float inv = 1.f / s;
        for (int k = 0; k < TOPK; k++) {
            w[k] *= inv;
            ew_out[warp * TOPK + k] = w[k];
            int p = atomicAdd(&g_count[idx[k]], 1);
            g_assign[idx[k] * NTOK + p] = warp * 4 + k;
        }
    }
}

// ====================================================================================
// GEMM1: act = SwiGLU(gather(x) @ w1^T + b1)   (128 thr, 4 warps 2x2, warp tile 64x64)
// ====================================================================================
__global__ __launch_bounds__(128, 2)
void gemm1_kernel(const float* __restrict__ b1) {
    extern __shared__ char smem[];
    const int e    = blockIdx.z;
    const int cnt  = g_count[e];
    const int row0 = blockIdx.y * MT;
    if (row0 >= cnt) return;
    const int col0 = blockIdx.x * NT;
    const int tid = threadIdx.x, lane = tid & 31, wid = tid >> 5;
    const int wm = wid >> 1, wn = wid & 1;
    uint32_t sb = smem_u32(smem);
    int* s_tok = (int*)smem;

    {
        int r = row0 + tid;
        s_tok[tid] = (r < cnt) ? (g_assign[e * NTOK + r] >> 2) : -1;
    }
    __syncthreads();

    float d[4][8][4];
#pragma unroll
    for (int mi = 0; mi < 4; mi++)
#pragma unroll
        for (int nt = 0; nt < 8; nt++)
#pragma unroll
            for (int r = 0; r < 4; r++) d[mi][nt][r] = 0.f;

    const __half* Bb = g_w1h + ((size_t)e * GUDIM + col0) * HDIM;
    const int lr = tid >> 3, lc = tid & 7;   // 16 rows-per-pass x 8 col-slots

    auto issue = [&](int cidx) {
        int p = cidx & 1, kt = cidx * KT;
        uint32_t a0 = sb + 1024 + p * FB_STAGE;
        uint32_t b0 = a0 + FB_TILE;
#pragma unroll
        for (int i = 0; i < 8; i++) {
            int r = lr + i * 16;
            int tok = s_tok[r];
            CPA16P(a0 + (r * 72 + lc * 8) * 2,
                   g_xh + (size_t)(tok < 0 ? 0 : tok) * HDIM + kt + lc * 8,
                   (tok >= 0) ? 16 : 0);
            CPA16(b0 + (r * 72 + lc * 8) * 2, Bb + (size_t)r * HDIM + kt + lc * 8);
        }
        CPA_COMMIT();
    };

    issue(0);
    for (int cc = 0; cc < NCHUNK; cc++) {
        int p = cc & 1;
        CPA_WAIT(0);
        __syncthreads();                    // all finished compute on buf p (prev use)
        if (cc + 1 < NCHUNK) issue(cc + 1); // safe: writes buf 1-p
        uint32_t sA = sb + 1024 + p * FB_STAGE;
        uint32_t sB = sA + FB_TILE;
        uint32_t aBase = sA + ((wm * 64 + (lane & 15)) * 72 + (lane >> 4) * 8) * 2;
        uint32_t bBase = sB + ((wn * 64 + (lane & 7) + (lane >> 4) * 8) * 72 +
                               ((lane >> 3) & 1) * 8) * 2;
#pragma unroll
        for (int kk = 0; kk < KT; kk += 16) {
            uint32_t a[4][4], b[4][4];
#pragma unroll
            for (int mi = 0; mi < 4; mi++)
                ldsm4(a[mi][0], a[mi][1], a[mi][2], a[mi][3],
                      aBase + (mi * 16 * 72 + kk) * 2);
#pragma unroll
            for (int g = 0; g < 4; g++)
                ldsm4(b[g][0], b[g][1], b[g][2], b[g][3],
                      bBase + (g * 16 * 72 + kk) * 2);
#pragma unroll
            for (int mi = 0; mi < 4; mi++)
#pragma unroll
                for (int g = 0; g < 4; g++) {
                    mma16816(d[mi][2 * g],     a[mi], b[g][0], b[g][1]);
                    mma16816(d[mi][2 * g + 1], a[mi], b[g][2], b[g][3]);
                }
        }
    }
    __syncthreads();   // buffers become staging area

    // epilogue: SwiGLU from register pairs; stage fp16 [128 rows][64 cols] pitch 72
    __half* st_h = (__half*)(smem + 1024);
    const float* bb = b1 + e * GUDIM + col0;
#pragma unroll
    for (int mi = 0; mi < 4; mi++) {
        int rbase = wm * 64 + mi * 16 + (lane >> 2);
#pragma unroll
        for (int nt = 0; nt < 8; nt++) {
            int gcl = wn * 64 + nt * 8 + (lane & 3) * 2;   // local gate col (even)
            float bg = bb[gcl], bu = bb[gcl + 1];
            int acl = (gcl >> 1);                          // local act col 0..63
#pragma unroll
            for (int h = 0; h < 2; h++) {
                float g = d[mi][nt][2 * h]     + bg;
                float u = d[mi][nt][2 * h + 1] + bu;
                g = fminf(g, 7.0f);
                u = fminf(fmaxf(u, -7.0f), 7.0f);
                float glu = g / (1.0f + expf(-1.702f * g));
                st_h[(rbase + 8 * h) * 72 + acl] = __float2half((u + 1.0f) * glu);
            }
        }
    }
    __syncthreads();
    {
        int rg = row0 + tid;
        if (rg < cnt) {
            __half* dst = g_act + ((size_t)e * NTOK + rg) * IDIM + (col0 >> 1);
            const __half* src = st_h + tid * 72;
#pragma unroll
            for (int j = 0; j < 8; j++)
                *(int4*)(dst + j * 8) = *(const int4*)(src + j * 8);
        }
    }
}

// ====================================================================================
// GEMM2: ebuf[assign] = act @ w2^T + b2   (direct float2 stores from registers)
// ====================================================================================
__global__ __launch_bounds__(128, 2)
void gemm2_kernel(const float* __restrict__ b2) {
    extern __shared__ char smem[];
    const int e    = blockIdx.z;
    const int cnt  = g_count[e];
    const int row0 = blockIdx.y * MT;
    if (row0 >= cnt) return;
    const int col0 = blockIdx.x * NT;
    const int tid = threadIdx.x, lane = tid & 31, wid = tid >> 5;
    const int wm = wid >> 1, wn = wid & 1;
    uint32_t sb = smem_u32(smem);
    int* s_asn = (int*)smem;

    {
        int r = row0 + tid;
        s_asn[tid] = (r < cnt) ? g_assign[e * NTOK + r] : -1;
    }
    __syncthreads();

    float d[4][8][4];
#pragma unroll
    for (int mi = 0; mi < 4; mi++)
#pragma unroll
        for (int nt = 0; nt < 8; nt++)
#pragma unroll
            for (int r = 0; r < 4; r++) d[mi][nt][r] = 0.f;

    const __half* Ab = g_act + ((size_t)e * NTOK + row0) * IDIM;
    const __half* Bb = g_w2h + (size_t)e * HDIM * IDIM + (size_t)col0 * IDIM;
    const int lr = tid >> 3, lc = tid & 7;

    auto issue = [&](int cidx) {
        int p = cidx & 1, kt = cidx * KT;
        uint32_t a0 = sb + 1024 + p * FB_STAGE;
        uint32_t b0 = a0 + FB_TILE;
#pragma unroll
        for (int i = 0; i < 8; i++) {
            int r = lr + i * 16;
            int ok = (s_asn[r] >= 0) ? 16 : 0;
            CPA16P(a0 + (r * 72 + lc * 8) * 2, Ab + (size_t)r * IDIM + kt + lc * 8, ok);
            CPA16(b0 + (r * 72 + lc * 8) * 2, Bb + (size_t)r * IDIM + kt + lc * 8);
        }
        CPA_COMMIT();
    };

    issue(0);
    for (int cc = 0; cc < NCHUNK; cc++) {
        int p = cc & 1;
        CPA_WAIT(0);
        __syncthreads();
        if (cc + 1 < NCHUNK) issue(cc + 1);
        uint32_t sA = sb + 1024 + p * FB_STAGE;
        uint32_t sB = sA + FB_TILE;
        uint32_t aBase = sA + ((wm * 64 + (lane & 15)) * 72 + (lane >> 4) * 8) * 2;
        uint32_t bBase = sB + ((wn * 64 + (lane & 7) + (lane >> 4) * 8) * 72 +
                               ((lane >> 3) & 1) * 8) * 2;
#pragma unroll
        for (int kk = 0; kk < KT; kk += 16) {
            uint32_t a[4][4], b[4][4];
#pragma unroll
            for (int mi = 0; mi < 4; mi++)
                ldsm4(a[mi][0], a[mi][1], a[mi][2], a[mi][3],
                      aBase + (mi * 16 * 72 + kk) * 2);
#pragma unroll
            for (int g = 0; g < 4; g++)
                ldsm4(b[g][0], b[g][1], b[g][2], b[g][3],
                      bBase + (g * 16 * 72 + kk) * 2);
#pragma unroll
            for (int mi = 0; mi < 4; mi++)
#pragma unroll
                for (int g = 0; g < 4; g++) {
                    mma16816(d[mi][2 * g],     a[mi], b[g][0], b[g][1]);
                    mma16816(d[mi][2 * g + 1], a[mi], b[g][2], b[g][3]);
                }
        }
    }

    // epilogue: bias + direct float2 scatter
    const float* bb = b2 + e * HDIM + col0;
#pragma unroll
    for (int mi = 0; mi < 4; mi++) {
        int rbase = wm * 64 + mi * 16 + (lane >> 2);
#pragma unroll
        for (int h = 0; h < 2; h++) {
            int rl = rbase + 8 * h;
            int a = s_asn[rl];
            if (a >= 0) {
                float* dst = g_ebuf + (size_t)a * HDIM + col0;
#pragma unroll
                for (int nt = 0; nt < 8; nt++) {
                    int cl = wn * 64 + nt * 8 + (lane & 3) * 2;
                    float2 o;
                    o.x = d[mi][nt][2 * h]     + bb[cl];
                    o.y = d[mi][nt][2 * h + 1] + bb[cl + 1];
                    *(float2*)(dst + cl) = o;
                }
            }
        }
    }
}

// ---------------- combine -----------------------------------------------------------
__global__ void combine_kernel(float* __restrict__ out) {
    const float* ew = out + (size_t)NTOK * HDIM;
    int stride = gridDim.x * blockDim.x;
    int n4 = NTOK * HDIM / 4;
    for (int v = blockIdx.x * blockDim.x + threadIdx.x; v < n4; v += stride) {
        int t  = v >> 8;
        int hc = v & 255;
        float w0 = ew[t * 4 + 0], w1v = ew[t * 4 + 1];
        float w2v = ew[t * 4 + 2], w3 = ew[t * 4 + 3];
        const float4* e0 = (const float4*)(g_ebuf + (size_t)(t * 4 + 0) * HDIM);
        const float4* e1 = (const float4*)(g_ebuf + (size_t)(t * 4 + 1) * HDIM);
        const float4* e2 = (const float4*)(g_ebuf + (size_t)(t * 4 + 2) * HDIM);
        const float4* e3 = (const float4*)(g_ebuf + (size_t)(t * 4 + 3) * HDIM);
        float4 r0 = e0[hc], r1 = e1[hc], r2 = e2[hc], r3 = e3[hc];
        float4 o;
        o.x = w0 * r0.x + w1v * r1.x + w2v * r2.x + w3 * r3.x;
        o.y = w0 * r0.y + w1v * r1.y + w2v * r2.y + w3 * r3.y;
        o.z = w0 * r0.z + w1v * r1.z + w2v * r2.z + w3 * r3.z;
        o.w = w0 * r0.w + w1v * r1.w + w2v * r2.w + w3 * r3.w;
        ((float4*)out)[v] = o;
    }
}

// ---------------- launch ------------------------------------------------------------
extern "C" void kernel_launch(void* const* d_in, const int* in_sizes, int n_in,
                              void* d_out, int out_size) {
    const float* x  = (const float*)d_in[0];
    const float* rw = (const float*)d_in[1];
    const float* rb = (const float*)d_in[2];
    const float* w1 = (const float*)d_in[3];
    const float* b1 = (const float*)d_in[4];
    const float* w2 = (const float*)d_in[5];
    const float* b2 = (const float*)d_in[6];
    float* out = (float*)d_out;

    cudaFuncSetAttribute(gemm1_kernel, cudaFuncAttributeMaxDynamicSharedMemorySize, SMEM_TOTAL);
    cudaFuncSetAttribute(gemm2_kernel, cudaFuncAttributeMaxDynamicSharedMemorySize, SMEM_TOTAL);

    zero_counts_kernel<<<1, 32>>>();
    cvt_x_kernel<<<1024, 256>>>(x);

    __half* w1h; cudaGetSymbolAddress((void**)&w1h, g_w1h);
    __half* w2h; cudaGetSymbolAddress((void**)&w2h, g_w2h);
    cvt_t_kernel<<<dim3(GUDIM / 32, HDIM / 32, NEXP), dim3(32, 8)>>>(w1, w1h, HDIM, GUDIM);
    cvt_t_kernel<<<dim3(HDIM / 32, IDIM / 32, NEXP), dim3(32, 8)>>>(w2, w2h, IDIM, HDIM);

    router_kernel<<<NTOK / 8, 256>>>(x, rw, rb, out + (size_t)NTOK * HDIM);

    gemm1_kernel<<<dim3(GUDIM / NT, NTOK / MT, NEXP), 128, SMEM_TOTAL>>>(b1);
    gemm2_kernel<<<dim3(HDIM  / NT, NTOK / MT, NEXP), 128, SMEM_TOTAL>>>(b2);

    combine_kernel<<<2048, 256>>>(out);
}

// round 9
// speedup vs baseline: 1.3149x; 1.0147x over previous
#include <cuda_runtime.h>
#include <cuda_fp16.h>
#include <cstdint>
#include <math.h>

#define NTOK  4096
#define HDIM  1024
#define IDIM  1024
#define NEXP  8
#define TOPK  4
#define GUDIM 2048

#define MT 128
#define NT 128
#define KT 64
#define NCHUNK 16

// smem: [0,512) row ints, buffers at 1024: 2 stages of (A 128x72 + B 128x72) halves
#define FB_TILE  (128 * 72 * 2)          // 18432 B
#define FB_STAGE (2 * FB_TILE)           // 36864 B
#define SMEM_TOTAL (1024 + 2 * FB_STAGE) // 74752 B -> 2 CTAs/SM

// ---------------- device scratch ----------------------------------------------------
__device__ __align__(16) __half g_xh [(size_t)NTOK * HDIM];
__device__ __align__(16) __half g_w1h[(size_t)NEXP * GUDIM * HDIM];   // [e][n][k]
__device__ __align__(16) __half g_w2h[(size_t)NEXP * HDIM * IDIM];    // [e][n][k]
__device__ __align__(16) __half g_act[(size_t)NEXP * NTOK * IDIM];
__device__ int g_count[NEXP];
__device__ int g_assign[NEXP * NTOK];

// ---------------- helpers -----------------------------------------------------------
__device__ __forceinline__ uint32_t smem_u32(const void* p) {
    uint32_t a;
    asm("{ .reg .u64 t; cvta.to.shared.u64 t, %1; cvt.u32.u64 %0, t; }" : "=r"(a) : "l"(p));
    return a;
}

#define CPA16(dst, src)       asm volatile("cp.async.cg.shared.global [%0], [%1], 16;"     :: "r"(dst), "l"(src))
#define CPA16P(dst, src, sz)  asm volatile("cp.async.cg.shared.global [%0], [%1], 16, %2;" :: "r"(dst), "l"(src), "r"(sz))
#define CPA_COMMIT()          asm volatile("cp.async.commit_group;" ::: "memory")
#define CPA_WAIT(n)           asm volatile("cp.async.wait_group %0;" :: "n"(n) : "memory")
#define RED2(p, x, y)         asm volatile("red.global.add.v2.f32 [%0], {%1, %2};" :: "l"(p), "f"(x), "f"(y) : "memory")

__device__ __forceinline__ void ldsm4(uint32_t& r0, uint32_t& r1, uint32_t& r2, uint32_t& r3,
                                      uint32_t addr) {
    asm volatile("ldmatrix.sync.aligned.m8n8.x4.shared.b16 {%0,%1,%2,%3}, [%4];"
                 : "=r"(r0), "=r"(r1), "=r"(r2), "=r"(r3) : "r"(addr));
}
__device__ __forceinline__ void mma16816(float* d, const uint32_t* a, uint32_t b0, uint32_t b1) {
    asm volatile("mma.sync.aligned.m16n8k16.row.col.f32.f16.f16.f32 "
                 "{%0,%1,%2,%3},{%4,%5,%6,%7},{%8,%9},{%0,%1,%2,%3};"
                 : "+f"(d[0]), "+f"(d[1]), "+f"(d[2]), "+f"(d[3])
                 : "r"(a[0]), "r"(a[1]), "r"(a[2]), "r"(a[3]), "r"(b0), "r"(b1));
}

// ---------------- tiny utility kernels ----------------------------------------------
__global__ void zero_counts_kernel() {
    if (threadIdx.x < NEXP) g_count[threadIdx.x] = 0;
}

__global__ void zero_out_kernel(float* __restrict__ out) {
    int stride = gridDim.x * blockDim.x;
    int n4 = NTOK * HDIM / 4;
    float4 z = make_float4(0.f, 0.f, 0.f, 0.f);
    for (int i = blockIdx.x * blockDim.x + threadIdx.x; i < n4; i += stride)
        ((float4*)out)[i] = z;
}

__global__ void cvt_x_kernel(const float* __restrict__ s) {
    int stride = gridDim.x * blockDim.x;
    int n4 = NTOK * HDIM / 4;
    for (int i = blockIdx.x * blockDim.x + threadIdx.x; i < n4; i += stride) {
        float4 v = ((const float4*)s)[i];
        __half2* d = (__half2*)(g_xh + (size_t)i * 4);
        d[0] = __floats2half2_rn(v.x, v.y);
        d[1] = __floats2half2_rn(v.z, v.w);
    }
}

// transpose-convert: s [z][K][N] fp32 -> d [z][N][K] fp16 (half2 coalesced writes)
__global__ void cvt_t_kernel(const float* __restrict__ s, __half* __restrict__ d,
                             int K, int N) {
    __shared__ float t[32][33];
    int n0 = blockIdx.x * 32, k0 = blockIdx.y * 32, z = blockIdx.z;
    const float* sp = s + (size_t)z * K * N;
    __half* dp = d + (size_t)z * K * N;
    int tx = threadIdx.x, ty = threadIdx.y;
#pragma unroll
    for (int i = 0; i < 32; i += 8)
        t[ty + i][tx] = sp[(size_t)(k0 + ty + i) * N + n0 + tx];
    __syncthreads();
    int id = ty * 32 + tx;
#pragma unroll
    for (int j = 0; j < 2; j++) {
        int v = id + j * 256;
        int r = v >> 4;
        int c = v & 15;
        __half2 h = __floats2half2_rn(t[c * 2][r], t[c * 2 + 1][r]);
        *(__half2*)(dp + (size_t)(n0 + r) * K + k0 + c * 2) = h;
    }
}

// ---------------- router ------------------------------------------------------------
__global__ void router_kernel(const float* __restrict__ x,
                              const float* __restrict__ rw,
                              const float* __restrict__ rb,
                              float* __restrict__ ew_out) {
    int warp = (blockIdx.x * blockDim.x + threadIdx.x) >> 5;
    int lane = threadIdx.x & 31;
    if (warp >= NTOK) return;
    const float* xr = x + (size_t)warp * HDIM;

    float acc[NEXP];
#pragma unroll
    for (int e = 0; e < NEXP; e++) acc[e] = 0.f;
    for (int h = lane; h < HDIM; h += 32) {
        float xv = xr[h];
#pragma unroll
        for (int e = 0; e < NEXP; e++) acc[e] += xv * rw[e * HDIM + h];
    }
#pragma unroll
    for (int e = 0; e < NEXP; e++) {
#pragma unroll
        for (int off = 16; off; off >>= 1)
            acc[e] += __shfl_xor_sync(0xffffffffu, acc[e], off);
    }
    if (lane == 0) {
        float lg[NEXP];
#pragma unroll
        for (int e = 0; e < NEXP; e++) lg[e] = acc[e] + rb[e];
        int idx[TOPK]; float val[TOPK]; bool used[NEXP];
#pragma unroll
        for (int e = 0; e < NEXP; e++) used[e] = false;
        for (int k = 0; k < TOPK; k++) {
            float best = -INFINITY; int bi = 0;
            for (int e = 0; e < NEXP; e++)
                if (!used[e] && lg[e] > best) { best = lg[e]; bi = e; }
            used[bi] = true; idx[k] = bi; val[k] = best;
        }
        float m = val[0], s = 0.f, w[TOPK];
        for (int k = 0; k < TOPK; k++) { w[k] = expf(val[k] - m); s += w[k]; }
        float inv = 1.f / s;
        for (int k = 0; k < TOPK; k++) {
            w[k] *= inv;
            ew_out[warp * TOPK + k] = w[k];
            int p = atomicAdd(&g_count[idx[k]], 1);
            g_assign[idx[k] * NTOK + p] = warp * 4 + k;
        }
    }
}

// ====================================================================================
// GEMM1: act = SwiGLU(gather(x) @ w1^T + b1)   (128 thr, 4 warps 2x2, warp tile 64x64)
// ====================================================================================
__global__ __launch_bounds__(128, 2)
void gemm1_kernel(const float* __restrict__ b1) {
    extern __shared__ char smem[];
    const int e    = blockIdx.z;
    const int cnt  = g_count[e];
    const int row0 = blockIdx.y * MT;
    if (row0 >= cnt) return;
    const int col0 = blockIdx.x * NT;
    const int tid = threadIdx.x, lane = tid & 31, wid = tid >> 5;
    const int wm = wid >> 1, wn = wid & 1;
    uint32_t sb = smem_u32(smem);
    int* s_tok = (int*)smem;

    {
        int r = row0 + tid;
        s_tok[tid] = (r < cnt) ? (g_assign[e * NTOK + r] >> 2) : -1;
    }
    __syncthreads();

    float d[4][8][4];
#pragma unroll
    for (int mi = 0; mi < 4; mi++)
#pragma unroll
        for (int nt = 0; nt < 8; nt++)
#pragma unroll
            for (int r = 0; r < 4; r++) d[mi][nt][r] = 0.f;

    const __half* Bb = g_w1h + ((size_t)e * GUDIM + col0) * HDIM;
    const int lr = tid >> 3, lc = tid & 7;   // 16 rows-per-pass x 8 col-slots

    auto issue = [&](int cidx) {
        int p = cidx & 1, kt = cidx * KT;
        uint32_t a0 = sb + 1024 + p * FB_STAGE;
        uint32_t b0 = a0 + FB_TILE;
#pragma unroll
        for (int i = 0; i < 8; i++) {
            int r = lr + i * 16;
            int tok = s_tok[r];
            CPA16P(a0 + (r * 72 + lc * 8) * 2,
                   g_xh + (size_t)(tok < 0 ? 0 : tok) * HDIM + kt + lc * 8,
                   (tok >= 0) ? 16 : 0);
            CPA16(b0 + (r * 72 + lc * 8) * 2, Bb + (size_t)r * HDIM + kt + lc * 8);
        }
        CPA_COMMIT();
    };

    issue(0);
    for (int cc = 0; cc < NCHUNK; cc++) {
        int p = cc & 1;
        CPA_WAIT(0);
        __syncthreads();
        if (cc + 1 < NCHUNK) issue(cc + 1);
        uint32_t sA = sb + 1024 + p * FB_STAGE;
        uint32_t sB = sA + FB_TILE;
        uint32_t aBase = sA + ((wm * 64 + (lane & 15)) * 72 + (lane >> 4) * 8) * 2;
        uint32_t bBase = sB + ((wn * 64 + (lane & 7) + (lane >> 4) * 8) * 72 +
                               ((lane >> 3) & 1) * 8) * 2;
#pragma unroll
        for (int kk = 0; kk < KT; kk += 16) {
            uint32_t a[4][4], b[4][4];
#pragma unroll
            for (int mi = 0; mi < 4; mi++)
                ldsm4(a[mi][0], a[mi][1], a[mi][2], a[mi][3],
                      aBase + (mi * 16 * 72 + kk) * 2);
#pragma unroll
            for (int g = 0; g < 4; g++)
                ldsm4(b[g][0], b[g][1], b[g][2], b[g][3],
                      bBase + (g * 16 * 72 + kk) * 2);
#pragma unroll
            for (int mi = 0; mi < 4; mi++)
#pragma unroll
                for (int g = 0; g < 4; g++) {
                    mma16816(d[mi][2 * g],     a[mi], b[g][0], b[g][1]);
                    mma16816(d[mi][2 * g + 1], a[mi], b[g][2], b[g][3]);
                }
        }
    }
    __syncthreads();   // buffers become staging area

    // epilogue: SwiGLU from register pairs; stage fp16 [128 rows][64 cols] pitch 72
    __half* st_h = (__half*)(smem + 1024);
    const float* bb = b1 + e * GUDIM + col0;
#pragma unroll
    for (int mi = 0; mi < 4; mi++) {
        int rbase = wm * 64 + mi * 16 + (lane >> 2);
#pragma unroll
        for (int nt = 0; nt < 8; nt++) {
            int gcl = wn * 64 + nt * 8 + (lane & 3) * 2;
            float bg = bb[gcl], bu = bb[gcl + 1];
            int acl = (gcl >> 1);
#pragma unroll
            for (int h = 0; h < 2; h++) {
                float g = d[mi][nt][2 * h]     + bg;
                float u = d[mi][nt][2 * h + 1] + bu;
                g = fminf(g, 7.0f);
                u = fminf(fmaxf(u, -7.0f), 7.0f);
                float glu = g / (1.0f + expf(-1.702f * g));
                st_h[(rbase + 8 * h) * 72 + acl] = __float2half((u + 1.0f) * glu);
            }
        }
    }
    __syncthreads();
    {
        int rg = row0 + tid;
        if (rg < cnt) {
            __half* dst = g_act + ((size_t)e * NTOK + rg) * IDIM + (col0 >> 1);
            const __half* src = st_h + tid * 72;
#pragma unroll
            for (int j = 0; j < 8; j++)
                *(int4*)(dst + j * 8) = *(const int4*)(src + j * 8);
        }
    }
}

// ====================================================================================
// GEMM2: out[token] += w * (act @ w2^T + b2)   (red.global.add.v2.f32 scatter)
// ====================================================================================
__global__ __launch_bounds__(128, 2)
void gemm2_kernel(const float* __restrict__ b2, float* __restrict__ out) {
    extern __shared__ char smem[];
    const int e    = blockIdx.z;
    const int cnt  = g_count[e];
    const int row0 = blockIdx.y * MT;
    if (row0 >= cnt) return;
    const int col0 = blockIdx.x * NT;
    const int tid = threadIdx.x, lane = tid & 31, wid = tid >> 5;
    const int wm = wid >> 1, wn = wid & 1;
    uint32_t sb = smem_u32(smem);
    int* s_asn = (int*)smem;

    {
        int r = row0 + tid;
        s_asn[tid] = (r < cnt) ? g_assign[e * NTOK + r] : -1;
    }
    __syncthreads();

    float d[4][8][4];
#pragma unroll
    for (int mi = 0; mi < 4; mi++)
#pragma unroll
        for (int nt = 0; nt < 8; nt++)
#pragma unroll
            for (int r = 0; r < 4; r++) d[mi][nt][r] = 0.f;

    const __half* Ab = g_act + ((size_t)e * NTOK + row0) * IDIM;
    const __half* Bb = g_w2h + (size_t)e * HDIM * IDIM + (size_t)col0 * IDIM;
    const int lr = tid >> 3, lc = tid & 7;

    auto issue = [&](int cidx) {
        int p = cidx & 1, kt = cidx * KT;
        uint32_t a0 = sb + 1024 + p * FB_STAGE;
        uint32_t b0 = a0 + FB_TILE;
#pragma unroll
        for (int i = 0; i < 8; i++) {
            int r = lr + i * 16;
            int ok = (s_asn[r] >= 0) ? 16 : 0;
            CPA16P(a0 + (r * 72 + lc * 8) * 2, Ab + (size_t)r * IDIM + kt + lc * 8, ok);
            CPA16(b0 + (r * 72 + lc * 8) * 2, Bb + (size_t)r * IDIM + kt + lc * 8);
        }
        CPA_COMMIT();
    };

    issue(0);
    for (int cc = 0; cc < NCHUNK; cc++) {
        int p = cc & 1;
        CPA_WAIT(0);
        __syncthreads();
        if (cc + 1 < NCHUNK) issue(cc + 1);
        uint32_t sA = sb + 1024 + p * FB_STAGE;
        uint32_t sB = sA + FB_TILE;
        uint32_t aBase = sA + ((wm * 64 + (lane & 15)) * 72 + (lane >> 4) * 8) * 2;
        uint32_t bBase = sB + ((wn * 64 + (lane & 7) + (lane >> 4) * 8) * 72 +
                               ((lane >> 3) & 1) * 8) * 2;
#pragma unroll
        for (int kk = 0; kk < KT; kk += 16) {
            uint32_t a[4][4], b[4][4];
#pragma unroll
            for (int mi = 0; mi < 4; mi++)
                ldsm4(a[mi][0], a[mi][1], a[mi][2], a[mi][3],
                      aBase + (mi * 16 * 72 + kk) * 2);
#pragma unroll
            for (int g = 0; g < 4; g++)
                ldsm4(b[g][0], b[g][1], b[g][2], b[g][3],
                      bBase + (g * 16 * 72 + kk) * 2);
#pragma unroll
            for (int mi = 0; mi < 4; mi++)
#pragma unroll
                for (int g = 0; g < 4; g++) {
                    mma16816(d[mi][2 * g],     a[mi], b[g][0], b[g][1]);
                    mma16816(d[mi][2 * g + 1], a[mi], b[g][2], b[g][3]);
                }
        }
    }

    // epilogue: weighted bias-add, reduce directly into out
    const float* ew = out + (size_t)NTOK * HDIM;
    const float* bb = b2 + e * HDIM + col0;
#pragma unroll
    for (int mi = 0; mi < 4; mi++) {
        int rbase = wm * 64 + mi * 16 + (lane >> 2);
#pragma unroll
        for (int h = 0; h < 2; h++) {
            int rl = rbase + 8 * h;
            int a = s_asn[rl];
            if (a >= 0) {
                float w = ew[a];                 // ew[token*4 + slot]
                int tok = a >> 2;
                float* dst = out + (size_t)tok * HDIM + col0;
#pragma unroll
                for (int nt = 0; nt < 8; nt++) {
                    int cl = wn * 64 + nt * 8 + (lane & 3) * 2;
                    float vx = (d[mi][nt][2 * h]     + bb[cl])     * w;
                    float vy = (d[mi][nt][2 * h + 1] + bb[cl + 1]) * w;
                    RED2(dst + cl, vx, vy);
                }
            }
        }
    }
}

// ---------------- launch ------------------------------------------------------------
extern "C" void kernel_launch(void* const* d_in, const int* in_sizes, int n_in,
                              void* d_out, int out_size) {
    const float* x  = (const float*)d_in[0];
    const float* rw = (const float*)d_in[1];
    const float* rb = (const float*)d_in[2];
    const float* w1 = (const float*)d_in[3];
    const float* b1 = (const float*)d_in[4];
    const float* w2 = (const float*)d_in[5];
    const float* b2 = (const float*)d_in[6];
    float* out = (float*)d_out;

    cudaFuncSetAttribute(gemm1_kernel, cudaFuncAttributeMaxDynamicSharedMemorySize, SMEM_TOTAL);
    cudaFuncSetAttribute(gemm2_kernel, cudaFuncAttributeMaxDynamicSharedMemorySize, SMEM_TOTAL);

    zero_counts_kernel<<<1, 32>>>();
    zero_out_kernel<<<2048, 256>>>(out);
    cvt_x_kernel<<<1024, 256>>>(x);

    __half* w1h; cudaGetSymbolAddress((void**)&w1h, g_w1h);
    __half* w2h; cudaGetSymbolAddress((void**)&w2h, g_w2h);
    cvt_t_kernel<<<dim3(GUDIM / 32, HDIM / 32, NEXP), dim3(32, 8)>>>(w1, w1h, HDIM, GUDIM);
    cvt_t_kernel<<<dim3(HDIM / 32, IDIM / 32, NEXP), dim3(32, 8)>>>(w2, w2h, IDIM, HDIM);

    router_kernel<<<NTOK / 8, 256>>>(x, rw, rb, out + (size_t)NTOK * HDIM);

    gemm1_kernel<<<dim3(GUDIM / NT, NTOK / MT, NEXP), 128, SMEM_TOTAL>>>(b1);
    gemm2_kernel<<<dim3(HDIM  / NT, NTOK / MT, NEXP), 128, SMEM_TOTAL>>>(b2, out);
}